// round 15
// baseline (speedup 1.0000x reference)
#include <cuda_runtime.h>
#include <cuda_fp16.h>
#include <cstdint>

// Problem shape (fixed by the reference)
#define BDIM 4096
#define NIN  2048
#define NOUT 2048
#define GS   8
#define KDIM (NIN * GS)     // 16384 contraction length
#define NBLK (KDIM / 32)    // 512 K-blocks of 32

// fp16 scratch, K-permuted within each 32-block:
//   value (g = i&3, k = 0..7) at byte (k>>1)*16 + (g>>1)*8 + (g&1)*4 + (k&1)*2
//   of the 64B block-row. One LDS.128 = full m16n8k16 fragment (both k-steps).
__device__ __half g_basisH[(size_t)BDIM * KDIM];
__device__ __half g_coefTH[(size_t)NBLK * NOUT * 32];
// split-K partial outputs (kz = 0,1), 67 MB
__device__ float g_part[(size_t)2 * BDIM * NOUT];

// ---------------------------------------------------------------------------
// helpers
// ---------------------------------------------------------------------------
__device__ __forceinline__ uint32_t smem_u32(const void* p) {
    return (uint32_t)__cvta_generic_to_shared(p);
}
__device__ __forceinline__ void cp_async16(uint32_t s, const void* g) {
    asm volatile("cp.async.cg.shared.global [%0], [%1], 16;\n" :: "r"(s), "l"(g));
}
__device__ __forceinline__ void mma_fp16(float* d, uint32_t a0, uint32_t a1,
                                         uint32_t a2, uint32_t a3,
                                         uint32_t b0, uint32_t b1) {
    asm volatile(
        "mma.sync.aligned.m16n8k16.row.col.f32.f16.f16.f32 "
        "{%0,%1,%2,%3},{%4,%5,%6,%7},{%8,%9},{%0,%1,%2,%3};\n"
        : "+f"(d[0]), "+f"(d[1]), "+f"(d[2]), "+f"(d[3])
        : "r"(a0), "r"(a1), "r"(a2), "r"(a3), "r"(b0), "r"(b1));
}
__device__ __forceinline__ uint32_t h2u(__half2 h) {
    return *(uint32_t*)&h;
}

// ---------------------------------------------------------------------------
// Fused preprocessing: blocks [0, 32768) basis, [32768, 36864) coefT.
// ---------------------------------------------------------------------------
#define BASIS_BLOCKS 32768
#define COEFT_BLOCKS 4096

__global__ void prep_kernel(const float* __restrict__ x,
                            const float* __restrict__ coef,
                            const float* __restrict__ grid) {
    if (blockIdx.x < BASIS_BLOCKS) {
        int t = blockIdx.x * blockDim.x + threadIdx.x;
        float xv = x[t];
        float e[GS];
        float s = 0.f;
#pragma unroll
        for (int k = 0; k < GS; k++) {
            float d = xv - __ldg(grid + k);
            e[k] = __expf(-5.0f * d * d);
            s += e[k];
        }
        float inv = 1.0f / (s + 1e-8f);
        int g = t & 3;
        char* base = (char*)g_basisH + (size_t)(t >> 2) * 64
                   + (g >> 1) * 8 + (g & 1) * 4;
#pragma unroll
        for (int c = 0; c < 4; c++) {
            __half2 v = __floats2half2_rn(e[2 * c] * inv, e[2 * c + 1] * inv);
            *(__half2*)(base + c * 16) = v;
        }
    } else {
        int idx = (blockIdx.x - BASIS_BLOCKS) * blockDim.x + threadIdx.x;
        int blk = idx >> 11, j = idx & (NOUT - 1);
        float v[4][8];
#pragma unroll
        for (int g = 0; g < 4; g++) {
            const float4* s =
                (const float4*)(coef + ((size_t)(blk * 4 + g) * NOUT + j) * GS);
            float4 lo = s[0], hi = s[1];
            v[g][0] = lo.x; v[g][1] = lo.y; v[g][2] = lo.z; v[g][3] = lo.w;
            v[g][4] = hi.x; v[g][5] = hi.y; v[g][6] = hi.z; v[g][7] = hi.w;
        }
        uint4* dst = (uint4*)((char*)g_coefTH + (size_t)idx * 64);
#pragma unroll
        for (int c = 0; c < 4; c++) {
            uint4 o;
            o.x = h2u(__floats2half2_rn(v[0][2 * c], v[0][2 * c + 1]));
            o.y = h2u(__floats2half2_rn(v[1][2 * c], v[1][2 * c + 1]));
            o.z = h2u(__floats2half2_rn(v[2][2 * c], v[2][2 * c + 1]));
            o.w = h2u(__floats2half2_rn(v[3][2 * c], v[3][2 * c + 1]));
            dst[c] = o;
        }
    }
}

// ---------------------------------------------------------------------------
// GEMM: out_partial = A @ B over this CTA's K-half. fp16 HMMA m16n8k16.
// CTA tile 128x64, BK=64, 8 warps = 2(M) x 2(N) x 2(K-split-in-CTA).
// gridDim.z = 2: split-K across CTAs (128 outer iters each) -> 2048 CTAs,
// 6.92 waves at occ 2 => ~1% tail (vs 15% @1024).
// All global pointers are running pointers (+const/iter); all smem fragment
// addresses are one base reg + immediates (parity-XOR is lane-invariant).
// ---------------------------------------------------------------------------
#define BM 128
#define BN 64
#define STG 4
#define AB  (128 * 128)        // 16 KB A tile (128 rows x 128B = 2 K-blocks)
#define BB  (2 * 64 * 64)      // 8 KB B tile
#define STB (AB + BB)          // 24 KB per stage
#define GEMM_SMEM (STG * STB)  // 98304 bytes
#define KT2 (NBLK / 4)         // 128 outer iterations per CTA (64 K-elems each)

__global__ __launch_bounds__(256, 2)
void gemm_kernel(void) {
    extern __shared__ __align__(128) char smem[];

    const int tid  = threadIdx.x;
    const int lane = tid & 31;
    const int wid  = tid >> 5;
    const int m0 = blockIdx.y * BM;
    const int n0 = blockIdx.x * BN;
    const int kz = blockIdx.z;
    const int wm_i = (wid >> 2) & 1;     // 2 warps along M (64 rows each)
    const int wn_i = (wid >> 1) & 1;     // 2 warps along N (32 cols each)
    const int kw   = wid & 1;            // intra-CTA K-split warp
    const int lr = lane >> 2;            // 0..7
    const int lc = lane & 3;             // 0..3

    // ---- running global pointers (advance by constants each load) ----
    const int rowA = tid >> 3, LA = tid & 7;        // A: 128 rows x 8 chunks
    const int jB = (tid >> 2) & 63, LB = tid & 3;   // B: 64 j x 4 chunks (x2 bb)
    const char* pA = (const char*)g_basisH
        + ((size_t)(m0 + rowA) * NBLK + (size_t)kz * 256) * 64 + LA * 16;
    const char* pB = (const char*)g_coefTH
        + ((size_t)kz * 256 + 0) * (NOUT * 64) + (size_t)(n0 + jB) * 64 + LB * 16;

    // ---- fixed smem destination offsets (parity-XOR same for all its) ----
    const uint32_t sb0 = smem_u32(smem);
    const uint32_t dA0 = rowA * 128 + ((LA * 16) ^ ((rowA & 1) * 64));
    const uint32_t dB0 = AB + jB * 64 + LB * 16;

    int ldst = 0;                         // next load stage
    auto load_tile = [&]() {
        uint32_t sbase = sb0 + ldst * STB;
#pragma unroll
        for (int it = 0; it < 4; it++)    // A: rows rowA + it*32 (parity same)
            cp_async16(sbase + dA0 + it * 4096, pA + it * (32 * NBLK * 64));
#pragma unroll
        for (int it = 0; it < 2; it++)    // B: bb = it
            cp_async16(sbase + dB0 + it * 4096, pB + it * (NOUT * 64));
        asm volatile("cp.async.commit_group;\n");
        pA += 128;                        // 2 K-blocks
        pB += 2 * NOUT * 64;
        ldst = (ldst + 1) & (STG - 1);
    };

    // ---- fixed smem fragment base offsets ----
    // A: r = wm_i*64 + (hm*2+m2)*16 + j8*8 + lr; parity(r) == parity(lr)
    const uint32_t aoffx = (kw * 64 + lc * 16) ^ ((lr & 1) * 64);
    const uint32_t Abase = (wm_i * 64 + lr) * 128 + aoffx;
    const uint32_t Bbase = AB + kw * 4096 + (wn_i * 32 + lr) * 64 + lc * 16;

    float acc[4][4][4];
#pragma unroll
    for (int mt = 0; mt < 4; mt++)
#pragma unroll
        for (int nt = 0; nt < 4; nt++)
#pragma unroll
            for (int r = 0; r < 4; r++) acc[mt][nt][r] = 0.f;

    // prologue: fill STG-1 stages
    load_tile(); load_tile(); load_tile();

    for (int s = 0; s < KT2; s++) {
        asm volatile("cp.async.wait_group %0;\n" :: "n"(STG - 2));
        __syncthreads();

        if (s + STG - 1 < KT2) load_tile();
        else asm volatile("cp.async.commit_group;\n");  // keep group counts uniform

        const char* As_ = smem + (s & (STG - 1)) * STB;
        const char* pa = As_ + Abase;
        const char* pb = As_ + Bbase;

        uint4 ub[4];
#pragma unroll
        for (int nt = 0; nt < 4; nt++)
            ub[nt] = *(const uint4*)(pb + nt * 512);

#pragma unroll
        for (int hm = 0; hm < 2; hm++) {
            uint4 ua[2][2];
#pragma unroll
            for (int m2 = 0; m2 < 2; m2++) {
                ua[m2][0] = *(const uint4*)(pa + hm * 4096 + m2 * 2048);
                ua[m2][1] = *(const uint4*)(pa + hm * 4096 + m2 * 2048 + 1024);
            }
#pragma unroll
            for (int m2 = 0; m2 < 2; m2++) {
#pragma unroll
                for (int nt = 0; nt < 4; nt++) {
                    float* d = acc[hm * 2 + m2][nt];
                    mma_fp16(d, ua[m2][0].x, ua[m2][1].x, ua[m2][0].y, ua[m2][1].y,
                             ub[nt].x, ub[nt].y);
                    mma_fp16(d, ua[m2][0].z, ua[m2][1].z, ua[m2][0].w, ua[m2][1].w,
                             ub[nt].z, ub[nt].w);
                }
            }
        }
    }

    // ---- intra-CTA kw reduction, then partial store ----
    __syncthreads();
    float* red = (float*)smem;
    const int pos = (wm_i * 2 + wn_i) * 2048;   // 64x32 fp32 region

    if (kw == 1) {
#pragma unroll
        for (int mt = 0; mt < 4; mt++) {
#pragma unroll
            for (int nt = 0; nt < 4; nt++) {
                int lrow = mt * 16 + lr, col = nt * 8 + lc * 2;
                *(float2*)(red + pos + lrow * 32 + col) =
                    make_float2(acc[mt][nt][0], acc[mt][nt][1]);
                *(float2*)(red + pos + (lrow + 8) * 32 + col) =
                    make_float2(acc[mt][nt][2], acc[mt][nt][3]);
            }
        }
    }
    __syncthreads();
    if (kw == 0) {
        float* part = g_part + (size_t)kz * BDIM * NOUT;
#pragma unroll
        for (int mt = 0; mt < 4; mt++) {
#pragma unroll
            for (int nt = 0; nt < 4; nt++) {
                int lrow = mt * 16 + lr, col = nt * 8 + lc * 2;
                float2 p0 = *(float2*)(red + pos + lrow * 32 + col);
                float2 p1 = *(float2*)(red + pos + (lrow + 8) * 32 + col);
                int r = m0 + wm_i * 64 + mt * 16 + lr;
                int c = n0 + wn_i * 32 + nt * 8 + lc * 2;
                *(float2*)(part + (size_t)r * NOUT + c) =
                    make_float2(acc[mt][nt][0] + p0.x, acc[mt][nt][1] + p0.y);
                *(float2*)(part + (size_t)(r + 8) * NOUT + c) =
                    make_float2(acc[mt][nt][2] + p1.x, acc[mt][nt][3] + p1.y);
            }
        }
    }
}

// ---------------------------------------------------------------------------
// Final reduce: out = part0 + part1 (float4-vectorized, deterministic)
// ---------------------------------------------------------------------------
__global__ void reduce_kernel(float* __restrict__ out) {
    int i = blockIdx.x * blockDim.x + threadIdx.x;  // over 2M float4
    const float4* p0 = (const float4*)g_part;
    const float4* p1 = (const float4*)(g_part + (size_t)BDIM * NOUT);
    float4 a = p0[i], b = p1[i];
    float4 o = make_float4(a.x + b.x, a.y + b.y, a.z + b.z, a.w + b.w);
    ((float4*)out)[i] = o;
}

// ---------------------------------------------------------------------------
// launch
// ---------------------------------------------------------------------------
extern "C" void kernel_launch(void* const* d_in, const int* in_sizes, int n_in,
                              void* d_out, int out_size) {
    const float* x    = (const float*)d_in[0];   // [4096, 2048]
    const float* coef = (const float*)d_in[1];   // [2048, 2048, 8]
    const float* grid = (const float*)d_in[2];   // [8]
    float* out = (float*)d_out;                  // [4096, 2048]
    (void)in_sizes; (void)n_in; (void)out_size;

    prep_kernel<<<BASIS_BLOCKS + COEFT_BLOCKS, 256>>>(x, coef, grid);

    cudaFuncSetAttribute(gemm_kernel,
                         cudaFuncAttributeMaxDynamicSharedMemorySize, GEMM_SMEM);
    dim3 g(NOUT / BN, BDIM / BM, 2);             // (32, 32, 2) = 2048 CTAs
    gemm_kernel<<<g, 256, GEMM_SMEM>>>();

    reduce_kernel<<<(BDIM * NOUT / 4) / 256, 256>>>(out);
}